// round 11
// baseline (speedup 1.0000x reference)
#include <cuda_runtime.h>
#include <cstdint>

#define NMAX 100000
#define EMAX 1600000
#define H 128
#define NB_SCAN 98            // ceil(NMAX/1024)

// Scratch (allocation-free __device__ globals, ~8 MB)
__device__ int   g_cnt[NMAX];
__device__ int   g_part[NMAX];
__device__ int   g_bsum[128];
__device__ int   g_boff[128];
__device__ int   g_rowstart[NMAX + 1];
__device__ int   g_cursor[NMAX];
__device__ float g_dinv[NMAX];
__device__ int   g_esrc[EMAX];

// ---------------------------------------------------------------------------
__global__ void k_zero(int n) {
    int i = blockIdx.x * blockDim.x + threadIdx.x;
    if (i < n) g_cnt[i] = 0;
}

__global__ void k_deg(const int* __restrict__ dst, int E) {
    int e = blockIdx.x * blockDim.x + threadIdx.x;
    if (e < E) atomicAdd(&g_cnt[dst[e]], 1);
}

// ---------------------------------------------------------------------------
// 3-phase exclusive scan over g_cnt -> g_rowstart (+ cursor, dinv)
// ---------------------------------------------------------------------------
__global__ __launch_bounds__(1024)
void k_scanA(int n) {
    __shared__ int sm[1024];
    int t = threadIdx.x;
    int i = blockIdx.x * 1024 + t;
    int v = (i < n) ? g_cnt[i] : 0;
    sm[t] = v;
    __syncthreads();
#pragma unroll
    for (int off = 1; off < 1024; off <<= 1) {
        int u = (t >= off) ? sm[t - off] : 0;
        __syncthreads();
        sm[t] += u;
        __syncthreads();
    }
    if (i < n) g_part[i] = sm[t] - v;
    if (t == 1023) g_bsum[blockIdx.x] = sm[t];
}

__global__ __launch_bounds__(128)
void k_scanB() {
    __shared__ int sm[128];
    int t = threadIdx.x;
    int v = (t < NB_SCAN) ? g_bsum[t] : 0;
    sm[t] = v;
    __syncthreads();
#pragma unroll
    for (int off = 1; off < 128; off <<= 1) {
        int u = (t >= off) ? sm[t - off] : 0;
        __syncthreads();
        sm[t] += u;
        __syncthreads();
    }
    g_boff[t] = sm[t] - v;
}

__global__ void k_scanC(int n, int E) {
    int i = blockIdx.x * blockDim.x + threadIdx.x;
    if (i < n) {
        int rs = g_part[i] + g_boff[i >> 10];
        g_rowstart[i] = rs;
        g_cursor[i]   = rs;
        g_dinv[i]     = rsqrtf((float)(g_cnt[i] + 1));
    }
    if (i == 0) g_rowstart[n] = E;
}

__global__ void k_fill(const int* __restrict__ src,
                       const int* __restrict__ dst, int E) {
    int e = blockIdx.x * blockDim.x + threadIdx.x;
    if (e < E) {
        int pos = atomicAdd(&g_cursor[dst[e]], 1);
        g_esrc[pos] = src[e];
    }
}

// ---------------------------------------------------------------------------
// Warp-specialized fused kernel.
// 256 threads: warps 0-3 = producers (gather 32-row tiles into agg[buf]),
// warps 4-7 = consumers (32x128 GEMM + bias + PReLU from agg[buf^1]).
// Double-buffered agg; iteration handoff via __syncthreads; consumers use
// named barrier 1 (128 threads) around Ws k-tile staging. Producers fill
// tile t+1 while consumers compute tile t -> gather hidden under FFMA.
// Static smem 42.2 KB -> 5 blocks/SM.
// ---------------------------------------------------------------------------
#define TR 32    // tile rows
#define KT 16
#define WR 132   // padded stride (floats)

__device__ __forceinline__ void gather_tile(const float4* __restrict__ x4,
                                            float* __restrict__ aggbuf,
                                            int row0, int n,
                                            int warp, int lane) {
    // 4 producer warps, 8 rows each
#pragma unroll 1
    for (int i = 0; i < 8; i++) {
        int r  = warp * 8 + i;
        int gr = row0 + r;
        float4 acc = make_float4(0.f, 0.f, 0.f, 0.f);
        if (gr < n) {
            float dd = g_dinv[gr];
            float sl = dd * dd;
            float4 xv = __ldg(&x4[gr * 32 + lane]);   // self-loop
            acc.x = xv.x * sl; acc.y = xv.y * sl;
            acc.z = xv.z * sl; acc.w = xv.w * sl;

            int beg = g_rowstart[gr];
            int end = g_rowstart[gr + 1];
            for (int j0 = beg; j0 < end; j0 += 32) {
                int jn = min(32, end - j0);
                int   s  = 0;
                float ds = 0.f;
                if (lane < jn) {
                    s  = g_esrc[j0 + lane];
                    ds = g_dinv[s];
                }
#pragma unroll 4
                for (int t = 0; t < jn; t++) {
                    int   ss = __shfl_sync(0xffffffffu, s, t);
                    float nm = __shfl_sync(0xffffffffu, ds, t) * dd;
                    float4 v = __ldg(&x4[ss * 32 + lane]);
                    acc.x += v.x * nm;
                    acc.y += v.y * nm;
                    acc.z += v.z * nm;
                    acc.w += v.w * nm;
                }
            }
        }
        *(float4*)&aggbuf[r * WR + lane * 4] = acc;   // conflict-free
    }
}

__global__ __launch_bounds__(256)
void k_fused(const float4* __restrict__ x4, const float* __restrict__ W,
             const float* __restrict__ b, const float* __restrict__ prelu_a,
             float* __restrict__ out, int n, int nt) {
    __shared__ float agg[2][TR * WR];   // 33.8 KB
    __shared__ float Ws[KT * WR];       //  8.4 KB

    int tid  = threadIdx.x;
    int lane = tid & 31;
    int warp = tid >> 5;
    bool producer = (warp < 4);
    int G = gridDim.x;

    // Consumer thread mapping (ctid in 0..127)
    int ctid = tid - 128;
    int tx = ctid & 15, ty = ctid >> 4;    // valid only for consumers
    int c0 = tx * 8;
    int r0 = ty * 4;

    float a = prelu_a[0];
    float bb[8];
    if (!producer) {
#pragma unroll
        for (int j = 0; j < 8; j++) bb[j] = b[c0 + j];
    }

    // Prologue: producers fill buffer 0 with this block's first tile.
    int ti0 = blockIdx.x;
    if (producer && ti0 < nt)
        gather_tile(x4, agg[0], ti0 * TR, n, warp, lane);
    __syncthreads();

    int idx = 0;
    for (int ti = ti0; ti < nt; ti += G, idx++) {
        int cur = idx & 1;

        if (producer) {
            // Fill next tile into the other buffer.
            int tnext = ti + G;
            if (tnext < nt)
                gather_tile(x4, agg[cur ^ 1], tnext * TR, n, warp, lane);
        } else {
            // GEMM on agg[cur] for tile ti.
            float* ag = agg[cur];
            int row0 = ti * TR;

            float acc[4][8];
#pragma unroll
            for (int i = 0; i < 4; i++)
#pragma unroll
                for (int j = 0; j < 8; j++) acc[i][j] = 0.f;

            for (int k0 = 0; k0 < 128; k0 += KT) {
                asm volatile("bar.sync 1, 128;" ::: "memory");
                // Stage Ws tile k-major: 128 cols x 16 k = 512 float4 / 128 thr.
#pragma unroll
                for (int it = 0; it < 4; it++) {
                    int i = ctid + it * 128;
                    int c = i >> 2, q = i & 3;
                    float4 v = ((const float4*)W)[c * 32 + (k0 >> 2) + q];
                    Ws[(q * 4 + 0) * WR + c] = v.x;
                    Ws[(q * 4 + 1) * WR + c] = v.y;
                    Ws[(q * 4 + 2) * WR + c] = v.z;
                    Ws[(q * 4 + 3) * WR + c] = v.w;
                }
                asm volatile("bar.sync 1, 128;" ::: "memory");

#pragma unroll
                for (int kk = 0; kk < KT; kk++) {
                    float xr[4];
#pragma unroll
                    for (int i = 0; i < 4; i++)
                        xr[i] = ag[(r0 + i) * WR + k0 + kk];
                    float4 w0 = *(const float4*)&Ws[kk * WR + c0];
                    float4 w1 = *(const float4*)&Ws[kk * WR + c0 + 4];
                    float wc[8] = {w0.x, w0.y, w0.z, w0.w,
                                   w1.x, w1.y, w1.z, w1.w};
#pragma unroll
                    for (int i = 0; i < 4; i++)
#pragma unroll
                        for (int j = 0; j < 8; j++)
                            acc[i][j] += xr[i] * wc[j];
                }
            }

            // Epilogue: bias + PReLU, store.
#pragma unroll
            for (int i = 0; i < 4; i++) {
                int r = row0 + r0 + i;
                if (r < n) {
                    float vals[8];
#pragma unroll
                    for (int j = 0; j < 8; j++) {
                        float v = acc[i][j] + bb[j];
                        vals[j] = v >= 0.f ? v : a * v;
                    }
                    float4* op = (float4*)out + r * 32 + (c0 >> 2);
                    op[0] = make_float4(vals[0], vals[1], vals[2], vals[3]);
                    op[1] = make_float4(vals[4], vals[5], vals[6], vals[7]);
                }
            }
        }
        __syncthreads();   // buffer handoff
    }
}

// ---------------------------------------------------------------------------
extern "C" void kernel_launch(void* const* d_in, const int* in_sizes, int n_in,
                              void* d_out, int out_size) {
    const float* x  = (const float*)d_in[0];
    const int*   ei = (const int*)d_in[1];      // int32 (JAX x64 disabled)
    const float* W  = (const float*)d_in[2];
    const float* b  = (const float*)d_in[3];
    const float* pa = (const float*)d_in[4];
    float* out = (float*)d_out;

    int n = in_sizes[0] / H;          // 100000
    int E = in_sizes[1] / 2;          // 1600000
    if (E > EMAX) E = EMAX;
    const int* src = ei;
    const int* dst = ei + E;

    int nt = (n + TR - 1) / TR;       // 3125 tiles
    int G  = 740;                     // 5 blocks/SM x 148 SMs
    if (G > nt) G = nt;

    k_zero <<<(n + 255) / 256, 256>>>(n);
    k_deg  <<<(E + 255) / 256, 256>>>(dst, E);
    k_scanA<<<NB_SCAN, 1024>>>(n);
    k_scanB<<<1, 128>>>();
    k_scanC<<<(n + 255) / 256, 256>>>(n, E);
    k_fill <<<(E + 255) / 256, 256>>>(src, dst, E);
    k_fused<<<G, 256>>>((const float4*)x, W, b, pa, out, n, nt);
}

// round 16
// speedup vs baseline: 1.3704x; 1.3704x over previous
#include <cuda_runtime.h>
#include <cuda_fp16.h>
#include <cstdint>

#define NMAX 100000
#define EMAX 1600000
#define H 128
#define NB_SCAN 98            // ceil(NMAX/1024)

// Scratch (allocation-free __device__ globals)
__device__ int    g_cnt[NMAX];         // zero at load; k_scanC re-zeros each call
__device__ int    g_part[NMAX];
__device__ int    g_bsum[128];
__device__ int    g_boff[128];
__device__ int    g_rowstart[NMAX + 1];
__device__ int    g_cursor[NMAX];
__device__ float  g_dinv[NMAX];
__device__ int    g_esrc[EMAX];
__device__ __half g_Wh[128 * 128];     // fp16 W, row-major W[c][k]

// ---------------------------------------------------------------------------
// Prep kernels
// ---------------------------------------------------------------------------
__global__ void k_deg(const int* __restrict__ dst, int E) {
    int e = blockIdx.x * blockDim.x + threadIdx.x;
    if (e < E) atomicAdd(&g_cnt[dst[e]], 1);
}

__global__ __launch_bounds__(1024)
void k_scanA(int n) {
    __shared__ int sm[1024];
    int t = threadIdx.x;
    int i = blockIdx.x * 1024 + t;
    int v = (i < n) ? g_cnt[i] : 0;
    sm[t] = v;
    __syncthreads();
#pragma unroll
    for (int off = 1; off < 1024; off <<= 1) {
        int u = (t >= off) ? sm[t - off] : 0;
        __syncthreads();
        sm[t] += u;
        __syncthreads();
    }
    if (i < n) g_part[i] = sm[t] - v;
    if (t == 1023) g_bsum[blockIdx.x] = sm[t];
}

__global__ __launch_bounds__(128)
void k_scanB() {
    __shared__ int sm[128];
    int t = threadIdx.x;
    int v = (t < NB_SCAN) ? g_bsum[t] : 0;
    sm[t] = v;
    __syncthreads();
#pragma unroll
    for (int off = 1; off < 128; off <<= 1) {
        int u = (t >= off) ? sm[t - off] : 0;
        __syncthreads();
        sm[t] += u;
        __syncthreads();
    }
    g_boff[t] = sm[t] - v;
}

__global__ void k_scanC(int n, int E) {
    int i = blockIdx.x * blockDim.x + threadIdx.x;
    if (i < n) {
        int rs = g_part[i] + g_boff[i >> 10];
        g_rowstart[i] = rs;
        g_cursor[i]   = rs;
        g_dinv[i]     = rsqrtf((float)(g_cnt[i] + 1));
        g_cnt[i]      = 0;                     // reset for next graph replay
    }
    if (i == 0) g_rowstart[n] = E;
}

__global__ void k_fill(const int* __restrict__ src,
                       const int* __restrict__ dst, int E) {
    int e = blockIdx.x * blockDim.x + threadIdx.x;
    if (e < E) {
        int pos = atomicAdd(&g_cursor[dst[e]], 1);
        g_esrc[pos] = src[e];
    }
}

__global__ void k_wconv(const float* __restrict__ W) {
    int i = blockIdx.x * blockDim.x + threadIdx.x;
    if (i < 128 * 128) g_Wh[i] = __float2half(W[i]);
}

// ---------------------------------------------------------------------------
// Fused gather + fp16 mma.sync GEMM + bias/PReLU epilogue.
// Tile: 128 rows x 128 cols. 8 warps in 4x2 grid; each warp 32x64 via
// m16n8k16 row.col f32.f16.f16.f32 (2 m-frags x 8 n-frags x 8 k-steps).
// A staged in smem (136-half row stride -> conflict-free fragment LDS);
// B fragments straight from g_Wh (L1-resident, 32 KB).
// ---------------------------------------------------------------------------
#define TILE_M 128
#define AS 136   // A row stride in halves

__global__ __launch_bounds__(256)
void k_fused(const float4* __restrict__ x4, const float* __restrict__ b,
             const float* __restrict__ prelu_a, float* __restrict__ out, int n) {
    __shared__ __align__(16) __half As[TILE_M * AS];   // 34.8 KB

    int tid  = threadIdx.x;
    int lane = tid & 31;
    int warp = tid >> 5;
    int row0 = blockIdx.x * TILE_M;

    // ---- Phase 1: gather (8 warps x 16 rows), fp32 accum -> fp16 smem ----
#pragma unroll 1
    for (int i = 0; i < 16; i++) {
        int r  = warp * 16 + i;
        int gr = row0 + r;
        float4 acc = make_float4(0.f, 0.f, 0.f, 0.f);
        if (gr < n) {
            float dd = g_dinv[gr];
            float sl = dd * dd;
            float4 xv = __ldg(&x4[gr * 32 + lane]);   // self-loop
            acc.x = xv.x * sl; acc.y = xv.y * sl;
            acc.z = xv.z * sl; acc.w = xv.w * sl;

            int beg = g_rowstart[gr];
            int end = g_rowstart[gr + 1];
            for (int j0 = beg; j0 < end; j0 += 32) {
                int jn = min(32, end - j0);
                int   s  = 0;
                float ds = 0.f;
                if (lane < jn) {
                    s  = g_esrc[j0 + lane];
                    ds = g_dinv[s];
                }
#pragma unroll 4
                for (int t = 0; t < jn; t++) {
                    int   ss = __shfl_sync(0xffffffffu, s, t);
                    float nm = __shfl_sync(0xffffffffu, ds, t) * dd;
                    float4 v = __ldg(&x4[ss * 32 + lane]);
                    acc.x += v.x * nm;
                    acc.y += v.y * nm;
                    acc.z += v.z * nm;
                    acc.w += v.w * nm;
                }
            }
        }
        __half2 p0 = __floats2half2_rn(acc.x, acc.y);
        __half2 p1 = __floats2half2_rn(acc.z, acc.w);
        *reinterpret_cast<uint2*>(&As[r * AS + lane * 4]) =
            make_uint2(*reinterpret_cast<uint32_t*>(&p0),
                       *reinterpret_cast<uint32_t*>(&p1));
    }
    __syncthreads();

    // ---- Phase 2: HMMA GEMM ----
    int wm = warp & 3;          // m tile: rows wm*32
    int wn = warp >> 2;         // n tile: cols wn*64
    int g  = lane >> 2;         // groupID
    int t2 = (lane & 3) * 2;    // threadID*2

    float acc[2][8][4];
#pragma unroll
    for (int mf = 0; mf < 2; mf++)
#pragma unroll
        for (int nf = 0; nf < 8; nf++)
#pragma unroll
            for (int q = 0; q < 4; q++) acc[mf][nf][q] = 0.f;

#pragma unroll
    for (int k0 = 0; k0 < 128; k0 += 16) {
        // A fragments (documented m16n8k16 mapping, plain LDS.32)
        uint32_t af[2][4];
#pragma unroll
        for (int mf = 0; mf < 2; mf++) {
            int rb = wm * 32 + mf * 16;
            af[mf][0] = *reinterpret_cast<const uint32_t*>(&As[(rb + g    ) * AS + k0 + t2    ]);
            af[mf][1] = *reinterpret_cast<const uint32_t*>(&As[(rb + g + 8) * AS + k0 + t2    ]);
            af[mf][2] = *reinterpret_cast<const uint32_t*>(&As[(rb + g    ) * AS + k0 + t2 + 8]);
            af[mf][3] = *reinterpret_cast<const uint32_t*>(&As[(rb + g + 8) * AS + k0 + t2 + 8]);
        }
        // B fragments from fp16 W (L1-resident)
        uint32_t bf[8][2];
#pragma unroll
        for (int nf = 0; nf < 8; nf++) {
            int cb = wn * 64 + nf * 8 + g;
            bf[nf][0] = __ldg(reinterpret_cast<const uint32_t*>(&g_Wh[cb * 128 + k0 + t2    ]));
            bf[nf][1] = __ldg(reinterpret_cast<const uint32_t*>(&g_Wh[cb * 128 + k0 + t2 + 8]));
        }
#pragma unroll
        for (int mf = 0; mf < 2; mf++)
#pragma unroll
            for (int nf = 0; nf < 8; nf++) {
                asm volatile(
                    "mma.sync.aligned.m16n8k16.row.col.f32.f16.f16.f32 "
                    "{%0,%1,%2,%3}, {%4,%5,%6,%7}, {%8,%9}, {%0,%1,%2,%3};"
                    : "+f"(acc[mf][nf][0]), "+f"(acc[mf][nf][1]),
                      "+f"(acc[mf][nf][2]), "+f"(acc[mf][nf][3])
                    : "r"(af[mf][0]), "r"(af[mf][1]),
                      "r"(af[mf][2]), "r"(af[mf][3]),
                      "r"(bf[nf][0]), "r"(bf[nf][1]));
            }
    }

    // ---- Epilogue: bias + PReLU, direct stores (float2 per row) ----
    float a = prelu_a[0];
#pragma unroll
    for (int nf = 0; nf < 8; nf++) {
        int col = wn * 64 + nf * 8 + t2;
        float bx = __ldg(b + col);
        float by = __ldg(b + col + 1);
#pragma unroll
        for (int mf = 0; mf < 2; mf++) {
            int r0 = row0 + wm * 32 + mf * 16 + g;
            float vx = acc[mf][nf][0] + bx;
            float vy = acc[mf][nf][1] + by;
            vx = vx >= 0.f ? vx : a * vx;
            vy = vy >= 0.f ? vy : a * vy;
            if (r0 < n)
                *reinterpret_cast<float2*>(out + (size_t)r0 * H + col) =
                    make_float2(vx, vy);
            int r1 = r0 + 8;
            float vz = acc[mf][nf][2] + bx;
            float vw = acc[mf][nf][3] + by;
            vz = vz >= 0.f ? vz : a * vz;
            vw = vw >= 0.f ? vw : a * vw;
            if (r1 < n)
                *reinterpret_cast<float2*>(out + (size_t)r1 * H + col) =
                    make_float2(vz, vw);
        }
    }
}

// ---------------------------------------------------------------------------
extern "C" void kernel_launch(void* const* d_in, const int* in_sizes, int n_in,
                              void* d_out, int out_size) {
    const float* x  = (const float*)d_in[0];
    const int*   ei = (const int*)d_in[1];      // int32 (JAX x64 disabled)
    const float* W  = (const float*)d_in[2];
    const float* b  = (const float*)d_in[3];
    const float* pa = (const float*)d_in[4];
    float* out = (float*)d_out;

    int n = in_sizes[0] / H;          // 100000
    int E = in_sizes[1] / 2;          // 1600000
    if (E > EMAX) E = EMAX;
    const int* src = ei;
    const int* dst = ei + E;

    int nt = (n + TILE_M - 1) / TILE_M;   // 782

    k_wconv<<<64, 256>>>(W);
    k_deg  <<<(E + 255) / 256, 256>>>(dst, E);
    k_scanA<<<NB_SCAN, 1024>>>(n);
    k_scanB<<<1, 128>>>();
    k_scanC<<<(n + 255) / 256, 256>>>(n, E);
    k_fill <<<(E + 255) / 256, 256>>>(src, dst, E);
    k_fused<<<nt, 256>>>((const float4*)x, b, pa, out, n);
}

// round 17
// speedup vs baseline: 1.4214x; 1.0373x over previous
#include <cuda_runtime.h>
#include <cuda_fp16.h>
#include <cstdint>

#define NMAX 100000
#define EMAX 1600000
#define H 128
#define NB_SCAN 98            // ceil(NMAX/1024)

// Scratch (allocation-free __device__ globals)
__device__ int    g_cnt[NMAX];         // zero at load; k_scanC re-zeros each call
__device__ int    g_part[NMAX];
__device__ int    g_bsum[128];
__device__ int    g_boff[128];
__device__ int    g_rowstart[NMAX + 1];
__device__ int    g_cursor[NMAX];
__device__ float  g_dinv[NMAX];
__device__ int    g_esrc[EMAX];
__device__ __half g_Wh[128 * 128];     // fp16 W, row-major W[c][k]
__device__ __half g_xh[NMAX * H];      // fp16 x image (25.6 MB, L2-resident)

// ---------------------------------------------------------------------------
// k_prep: merged degree-count + x fp16 conversion + W fp16 conversion.
// Block roles interleaved via bid%3 so atomic-bound and BW-bound streams
// overlap chip-wide. deg: 6250 blocks, xconv: 12500 blocks (ratio 1:2),
// wconv: 32 trailing blocks.
// ---------------------------------------------------------------------------
#define DEG_B   6250
#define XC_B    12500
#define PREP_B  (DEG_B + XC_B)          // 18750 (role-interleaved)
#define PREP_G  (PREP_B + 32)           // + wconv tail

__global__ void k_prep(const int* __restrict__ dst, int E,
                       const float4* __restrict__ x4, int nf4,
                       const float2* __restrict__ W2) {
    int bid = blockIdx.x;
    int tid = threadIdx.x;
    if (bid < PREP_B) {
        int r = bid % 3;
        if (r == 0) {                       // degree count
            int e = (bid / 3) * 256 + tid;
            if (e < E) atomicAdd(&g_cnt[dst[e]], 1);
        } else {                            // x fp32 -> fp16
            int id = (bid / 3) * 2 + (r - 1);
            int i  = id * 256 + tid;
            if (i < nf4) {
                float4 v = x4[i];
                __half2 p0 = __floats2half2_rn(v.x, v.y);
                __half2 p1 = __floats2half2_rn(v.z, v.w);
                reinterpret_cast<uint2*>(g_xh)[i] =
                    make_uint2(*reinterpret_cast<uint32_t*>(&p0),
                               *reinterpret_cast<uint32_t*>(&p1));
            }
        }
    } else {                                // W fp32 -> fp16 (8192 half2)
        int i = (bid - PREP_B) * 256 + tid;
        if (i < 128 * 64) {
            float2 v = W2[i];
            reinterpret_cast<__half2*>(g_Wh)[i] = __floats2half2_rn(v.x, v.y);
        }
    }
}

// ---------------------------------------------------------------------------
// 3-phase exclusive scan over g_cnt -> g_rowstart (+ cursor, dinv, reset)
// ---------------------------------------------------------------------------
__global__ __launch_bounds__(1024)
void k_scanA(int n) {
    __shared__ int sm[1024];
    int t = threadIdx.x;
    int i = blockIdx.x * 1024 + t;
    int v = (i < n) ? g_cnt[i] : 0;
    sm[t] = v;
    __syncthreads();
#pragma unroll
    for (int off = 1; off < 1024; off <<= 1) {
        int u = (t >= off) ? sm[t - off] : 0;
        __syncthreads();
        sm[t] += u;
        __syncthreads();
    }
    if (i < n) g_part[i] = sm[t] - v;
    if (t == 1023) g_bsum[blockIdx.x] = sm[t];
}

__global__ __launch_bounds__(128)
void k_scanB() {
    __shared__ int sm[128];
    int t = threadIdx.x;
    int v = (t < NB_SCAN) ? g_bsum[t] : 0;
    sm[t] = v;
    __syncthreads();
#pragma unroll
    for (int off = 1; off < 128; off <<= 1) {
        int u = (t >= off) ? sm[t - off] : 0;
        __syncthreads();
        sm[t] += u;
        __syncthreads();
    }
    g_boff[t] = sm[t] - v;
}

__global__ void k_scanC(int n, int E) {
    int i = blockIdx.x * blockDim.x + threadIdx.x;
    if (i < n) {
        int rs = g_part[i] + g_boff[i >> 10];
        g_rowstart[i] = rs;
        g_cursor[i]   = rs;
        g_dinv[i]     = rsqrtf((float)(g_cnt[i] + 1));
        g_cnt[i]      = 0;                     // reset for next graph replay
    }
    if (i == 0) g_rowstart[n] = E;
}

__global__ void k_fill(const int* __restrict__ src,
                       const int* __restrict__ dst, int E) {
    int e = blockIdx.x * blockDim.x + threadIdx.x;
    if (e < E) {
        int pos = atomicAdd(&g_cursor[dst[e]], 1);
        g_esrc[pos] = src[e];
    }
}

// ---------------------------------------------------------------------------
// Fused gather (fp16 x-image, fp32 accum) + fp16 mma.sync GEMM + epilogue.
// 128x128 tile, 8 warps 4x2, m16n8k16 f32.f16.f16.f32. 2 blocks/SM pinned.
// ---------------------------------------------------------------------------
#define TILE_M 128
#define AS 136   // A row stride in halves

__global__ __launch_bounds__(256, 2)
void k_fused(const float* __restrict__ b, const float* __restrict__ prelu_a,
             float* __restrict__ out, int n) {
    __shared__ __align__(16) __half As[TILE_M * AS];   // 34.8 KB

    int tid  = threadIdx.x;
    int lane = tid & 31;
    int warp = tid >> 5;
    int row0 = blockIdx.x * TILE_M;
    const uint2* xh = reinterpret_cast<const uint2*>(g_xh);  // 4 halves/lane

    // ---- Phase 1: gather (8 warps x 16 rows), fp16 rows, fp32 accum ----
#pragma unroll 1
    for (int i = 0; i < 16; i++) {
        int r  = warp * 16 + i;
        int gr = row0 + r;
        float4 acc = make_float4(0.f, 0.f, 0.f, 0.f);
        if (gr < n) {
            float dd = g_dinv[gr];
            float sl = dd * dd;
            uint2 hv = __ldg(&xh[gr * 32 + lane]);   // self-loop
            float2 l0 = __half22float2(*reinterpret_cast<__half2*>(&hv.x));
            float2 l1 = __half22float2(*reinterpret_cast<__half2*>(&hv.y));
            acc.x = l0.x * sl; acc.y = l0.y * sl;
            acc.z = l1.x * sl; acc.w = l1.y * sl;

            int beg = g_rowstart[gr];
            int end = g_rowstart[gr + 1];
            for (int j0 = beg; j0 < end; j0 += 32) {
                int jn = min(32, end - j0);
                int   s  = 0;
                float ds = 0.f;
                if (lane < jn) {
                    s  = g_esrc[j0 + lane];
                    ds = g_dinv[s];
                }
#pragma unroll 4
                for (int t = 0; t < jn; t++) {
                    int   ss = __shfl_sync(0xffffffffu, s, t);
                    float nm = __shfl_sync(0xffffffffu, ds, t) * dd;
                    uint2 hvv = __ldg(&xh[ss * 32 + lane]);
                    float2 e0 = __half22float2(*reinterpret_cast<__half2*>(&hvv.x));
                    float2 e1 = __half22float2(*reinterpret_cast<__half2*>(&hvv.y));
                    acc.x += e0.x * nm;
                    acc.y += e0.y * nm;
                    acc.z += e1.x * nm;
                    acc.w += e1.y * nm;
                }
            }
        }
        __half2 p0 = __floats2half2_rn(acc.x, acc.y);
        __half2 p1 = __floats2half2_rn(acc.z, acc.w);
        *reinterpret_cast<uint2*>(&As[r * AS + lane * 4]) =
            make_uint2(*reinterpret_cast<uint32_t*>(&p0),
                       *reinterpret_cast<uint32_t*>(&p1));
    }
    __syncthreads();

    // ---- Phase 2: HMMA GEMM ----
    int wm = warp & 3;          // m tile: rows wm*32
    int wn = warp >> 2;         // n tile: cols wn*64
    int g  = lane >> 2;         // groupID
    int t2 = (lane & 3) * 2;    // threadID*2

    float acc[2][8][4];
#pragma unroll
    for (int mf = 0; mf < 2; mf++)
#pragma unroll
        for (int nf = 0; nf < 8; nf++)
#pragma unroll
            for (int q = 0; q < 4; q++) acc[mf][nf][q] = 0.f;

#pragma unroll
    for (int k0 = 0; k0 < 128; k0 += 16) {
        uint32_t af[2][4];
#pragma unroll
        for (int mf = 0; mf < 2; mf++) {
            int rb = wm * 32 + mf * 16;
            af[mf][0] = *reinterpret_cast<const uint32_t*>(&As[(rb + g    ) * AS + k0 + t2    ]);
            af[mf][1] = *reinterpret_cast<const uint32_t*>(&As[(rb + g + 8) * AS + k0 + t2    ]);
            af[mf][2] = *reinterpret_cast<const uint32_t*>(&As[(rb + g    ) * AS + k0 + t2 + 8]);
            af[mf][3] = *reinterpret_cast<const uint32_t*>(&As[(rb + g + 8) * AS + k0 + t2 + 8]);
        }
        uint32_t bf[8][2];
#pragma unroll
        for (int nf = 0; nf < 8; nf++) {
            int cb = wn * 64 + nf * 8 + g;
            bf[nf][0] = __ldg(reinterpret_cast<const uint32_t*>(&g_Wh[cb * 128 + k0 + t2    ]));
            bf[nf][1] = __ldg(reinterpret_cast<const uint32_t*>(&g_Wh[cb * 128 + k0 + t2 + 8]));
        }
#pragma unroll
        for (int mf = 0; mf < 2; mf++)
#pragma unroll
            for (int nf = 0; nf < 8; nf++) {
                asm volatile(
                    "mma.sync.aligned.m16n8k16.row.col.f32.f16.f16.f32 "
                    "{%0,%1,%2,%3}, {%4,%5,%6,%7}, {%8,%9}, {%0,%1,%2,%3};"
                    : "+f"(acc[mf][nf][0]), "+f"(acc[mf][nf][1]),
                      "+f"(acc[mf][nf][2]), "+f"(acc[mf][nf][3])
                    : "r"(af[mf][0]), "r"(af[mf][1]),
                      "r"(af[mf][2]), "r"(af[mf][3]),
                      "r"(bf[nf][0]), "r"(bf[nf][1]));
            }
    }

    // ---- Epilogue: bias + PReLU, float2 stores ----
    float a = prelu_a[0];
#pragma unroll
    for (int nf = 0; nf < 8; nf++) {
        int col = wn * 64 + nf * 8 + t2;
        float bx = __ldg(b + col);
        float by = __ldg(b + col + 1);
#pragma unroll
        for (int mf = 0; mf < 2; mf++) {
            int r0 = row0 + wm * 32 + mf * 16 + g;
            float vx = acc[mf][nf][0] + bx;
            float vy = acc[mf][nf][1] + by;
            vx = vx >= 0.f ? vx : a * vx;
            vy = vy >= 0.f ? vy : a * vy;
            if (r0 < n)
                *reinterpret_cast<float2*>(out + (size_t)r0 * H + col) =
                    make_float2(vx, vy);
            int r1 = r0 + 8;
            float vz = acc[mf][nf][2] + bx;
            float vw = acc[mf][nf][3] + by;
            vz = vz >= 0.f ? vz : a * vz;
            vw = vw >= 0.f ? vw : a * vw;
            if (r1 < n)
                *reinterpret_cast<float2*>(out + (size_t)r1 * H + col) =
                    make_float2(vz, vw);
        }
    }
}

// ---------------------------------------------------------------------------
extern "C" void kernel_launch(void* const* d_in, const int* in_sizes, int n_in,
                              void* d_out, int out_size) {
    const float* x  = (const float*)d_in[0];
    const int*   ei = (const int*)d_in[1];      // int32 (JAX x64 disabled)
    const float* W  = (const float*)d_in[2];
    const float* b  = (const float*)d_in[3];
    const float* pa = (const float*)d_in[4];
    float* out = (float*)d_out;

    int n = in_sizes[0] / H;          // 100000
    int E = in_sizes[1] / 2;          // 1600000
    if (E > EMAX) E = EMAX;
    const int* src = ei;
    const int* dst = ei + E;

    int nt  = (n + TILE_M - 1) / TILE_M;   // 782
    int nf4 = n * 32;                      // float4 count of x

    k_prep <<<PREP_G, 256>>>(dst, E, (const float4*)x, nf4, (const float2*)W);
    k_scanA<<<NB_SCAN, 1024>>>(n);
    k_scanB<<<1, 128>>>();
    k_scanC<<<(n + 255) / 256, 256>>>(n, E);
    k_fill <<<(E + 255) / 256, 256>>>(src, dst, E);
    k_fused<<<nt, 256>>>(b, pa, out, n);
}